// round 14
// baseline (speedup 1.0000x reference)
#include <cuda_runtime.h>
#include <cuda_fp16.h>
#include <cstdint>

typedef unsigned int u32;

#define BB 4
#define HID 512
#define GG 20
#define NN (32*32*9)
#define MM (4*32*32)
#define KK (2048*9)
#define KTILES 576              /* 9 taps x 64 channel-chunks of 32 */
#define A_BYTES 10240           /* 128 rows * 80B (32 halves + 8 pad) */
#define B_BYTES 8192            /* 128 n * 32 k * 2B, fragment-packed */
#define STAGE_BYTES (A_BYTES + B_BYTES)   /* 18432 */
#define SMEM_BYTES (3*STAGE_BYTES)        /* 55296 */
#define NFMT (MM*2048)          /* halves: 8388608  */
#define NWF (512*18432)         /* halves: 9437184  */
#define EPSF 1e-8f

/* ---------------- scratch (static device globals; no allocation) ------- */
__device__ uint4 g_fmt4[NFMT/8];              /* pixel-major fp16 input [pix][c] */
__device__ uint4 g_wf4[NWF/8];                /* fragment-packed fp16 weights    */
__device__ float g_hid[MM * HID];             /* relu(conv1) pixel-major         */
__device__ float g_po[MM * 45];               /* per pixel: 9 conf + 36 reg      */
__device__ float g_maxpg[BB * GG];
__device__ float g_clsp[144];
__device__ float g_regp[144];

/* ---------------- helpers ---------------------------------------------- */
__device__ __forceinline__ u32 s2u(const void* p) {
    u32 a;
    asm("{ .reg .u64 t; cvta.to.shared.u64 t, %1; cvt.u32.u64 %0, t; }" : "=r"(a) : "l"(p));
    return a;
}
__device__ __forceinline__ void cpa16(u32 dst, const void* src) {
    asm volatile("cp.async.cg.shared.global [%0], [%1], 16;" :: "r"(dst), "l"(src));
}
__device__ __forceinline__ void cpa16z(u32 dst, const void* src, int srcsize) {
    asm volatile("cp.async.cg.shared.global [%0], [%1], 16, %2;"
                 :: "r"(dst), "l"(src), "r"(srcsize));
}
#define CP_COMMIT() asm volatile("cp.async.commit_group;" ::: "memory")
#define CP_WAIT1()  asm volatile("cp.async.wait_group 1;" ::: "memory")

__device__ __forceinline__ void ldsm4(u32& r0, u32& r1, u32& r2, u32& r3, u32 addr) {
    asm volatile("ldmatrix.sync.aligned.m8n8.x4.shared.b16 {%0,%1,%2,%3}, [%4];"
                 : "=r"(r0), "=r"(r1), "=r"(r2), "=r"(r3) : "r"(addr));
}
__device__ __forceinline__ void mma_f16(float& d0, float& d1, float& d2, float& d3,
                                        u32 a0, u32 a1, u32 a2, u32 a3,
                                        u32 b0, u32 b1) {
    asm volatile(
        "mma.sync.aligned.m16n8k16.row.col.f32.f16.f16.f32 "
        "{%0,%1,%2,%3}, {%4,%5,%6,%7}, {%8,%9}, {%0,%1,%2,%3};"
        : "+f"(d0), "+f"(d1), "+f"(d2), "+f"(d3)
        : "r"(a0), "r"(a1), "r"(a2), "r"(a3), "r"(b0), "r"(b1));
}
__device__ __forceinline__ float softplusf(float z) {
    return fmaxf(z, 0.f) + log1pf(expf(-fabsf(z)));
}
__device__ __forceinline__ void anchor_of(int n, float& x1, float& y1, float& x2,
                                          float& y2, float& areaA) {
    int cell = n / 9;  int a = n - cell * 9;
    int yI = cell >> 5, xI = cell & 31;
    int s = a / 3;     int r = a - s * 3;
    float aw = (float)(2 * (s + 1));
    float ah = __fmul_rn(aw, 0.5f + 0.5f * (float)r);
    float xc = (float)xI + 0.5f, yc = (float)yI + 0.5f;
    float hx = __fmul_rn(0.5f, aw), hy = __fmul_rn(0.5f, ah);
    x1 = fminf(fmaxf(__fsub_rn(xc, hx), 0.f), 32.f);
    y1 = fminf(fmaxf(__fsub_rn(yc, hy), 0.f), 32.f);
    x2 = fminf(fmaxf(__fadd_rn(xc, hx), 0.f), 32.f);
    y2 = fminf(fmaxf(__fadd_rn(yc, hy), 0.f), 32.f);
    areaA = __fmul_rn(__fsub_rn(x2, x1), __fsub_rn(y2, y1));
}
__device__ __forceinline__ float iou_f(float ax1, float ay1, float ax2, float ay2,
                                       float areaA, float gx1, float gy1, float gx2,
                                       float gy2, float areaG) {
    float lx = fmaxf(ax1, gx1), ly = fmaxf(ay1, gy1);
    float rx = fminf(ax2, gx2), ry = fminf(ay2, gy2);
    float iw = fmaxf(__fsub_rn(rx, lx), 0.f);
    float ih = fmaxf(__fsub_rn(ry, ly), 0.f);
    float inter = __fmul_rn(iw, ih);
    float den = __fadd_rn(__fsub_rn(__fadd_rn(areaA, areaG), inter), EPSF);
    return __fdiv_rn(inter, den);
}

/* ============ kernel 0a: transpose fm to pixel-major fp16 =============== */
__global__ __launch_bounds__(256) void k_fmt(const float* __restrict__ fm) {
    __shared__ float t[32][33];
    int pb = blockIdx.x * 32, cb = blockIdx.y * 32, b = blockIdx.z;
    int tx = threadIdx.x, ty = threadIdx.y;
    __half* gf = (__half*)g_fmt4;
#pragma unroll
    for (int i = ty; i < 32; i += 8)
        t[i][tx] = __ldg(fm + ((size_t)(b * 2048 + cb + i) << 10) + pb + tx);
    __syncthreads();
#pragma unroll
    for (int i = ty; i < 32; i += 8)
        gf[(((size_t)(b * 1024 + pb + i)) << 11) + cb + tx] = __float2half(t[tx][i]);
}

/* ============ kernel 0b: repack weights into fp16 mma-fragment order ==== */
__global__ __launch_bounds__(256) void k_wpack(const float* __restrict__ w1) {
    __shared__ float s[32][289];
    int cb = blockIdx.x;
    int nb = blockIdx.y;
    int n0b = nb * 32;
    int nt = nb >> 2, wn = nb & 3;
    int tid = threadIdx.x;
    __half* gw = (__half*)g_wf4;
    for (int idx = tid; idx < 32 * 288; idx += 256) {
        int r = idx / 288, cc = idx - r * 288;
        s[r][cc] = __ldg(w1 + (size_t)(n0b + r) * KK + cb * 288 + cc);
    }
    __syncthreads();
    for (int t = 0; t < 9; t++) {
        size_t base = ((size_t)(nt * 576 + t * 64 + cb)) * 4096 + wn * 1024;
#pragma unroll
        for (int q = 0; q < 4; q++) {
            int o = q * 256 + tid;
            int h8 = o & 7, lane = (o >> 3) & 31;
            int chunk = (o >> 8) & 1, ks = o >> 9;
            int j = chunk * 2 + (h8 >> 2);
            int r = (h8 >> 1) & 1, hh = h8 & 1;
            int g = lane >> 2, tig = lane & 3;
            int nloc = j * 8 + g;
            int klocal = ks * 16 + r * 8 + 2 * tig + hh;
            gw[base + o] = __float2half(s[nloc][klocal * 9 + t]);
        }
    }
}

/* ============ kernel 1: conv1, fp16 HMMA + ldmatrix, cp.async pipeline == */
__global__ __launch_bounds__(256, 1) void k_convmma(const float* __restrict__ b1) {
    extern __shared__ float sm[];
    const u32 sm0 = s2u(sm);
    const int tid = threadIdx.x;
    const int lane = tid & 31, wid = tid >> 5;
    const int g = lane >> 2, tig = lane & 3;
    const int wm = wid >> 2, wn = wid & 3;
    const int m0 = blockIdx.x * 128;
    const int nt = blockIdx.y;

    const int pp = tid >> 1, hseg = tid & 1;
    const int mp = m0 + pp;
    const int bbp = mp >> 10, yp = (mp >> 5) & 31, xp = mp & 31;

    const u32 aoff = (u32)((wm * 64 + (lane & 7) + ((lane >> 3) & 1) * 8) * 80
                           + ((lane >> 4) & 1) * 16);

    float acc[4][4][4];
#pragma unroll
    for (int i = 0; i < 4; i++)
#pragma unroll
        for (int j = 0; j < 4; j++)
#pragma unroll
            for (int c = 0; c < 4; c++) acc[i][j][c] = 0.f;

#define ISSUE(it, s) do {                                                      \
        int tap = (it) >> 6;                                                   \
        int c0 = ((it) & 63) << 5;                                             \
        u32 aB = sm0 + (u32)((s) * STAGE_BYTES);                               \
        {                                                                      \
            const uint4* srcB = g_wf4 + (size_t)(nt * 576 + (it)) * 512        \
                                + tid * 2;                                     \
            u32 dB = aB + A_BYTES + (u32)tid * 32;                             \
            cpa16(dB, srcB); cpa16(dB + 16, srcB + 1);                         \
        }                                                                      \
        {                                                                      \
            int dy = tap / 3 - 1, dx = tap - (tap / 3) * 3 - 1;                \
            int yy = yp + dy, xx = xp + dx;                                    \
            int vs = ((unsigned)yy < 32u && (unsigned)xx < 32u) ? 16 : 0;      \
            const uint4* srcA = vs ? g_fmt4 +                                  \
                ((size_t)((bbp << 10) + (yy << 5) + xx)) * 256                 \
                + (c0 >> 3) + hseg * 2 : g_fmt4;                               \
            u32 dA = aB + (u32)(pp * 80 + hseg * 32);                          \
            cpa16z(dA, srcA, vs); cpa16z(dA + 16, srcA + 1, vs);               \
        }                                                                      \
    } while (0)

    ISSUE(0, 0); CP_COMMIT();
    ISSUE(1, 1); CP_COMMIT();

    for (int it = 0; it < KTILES; it++) {
        CP_WAIT1();
        __syncthreads();
        const int s = it % 3;
        if (it + 2 < KTILES) ISSUE(it + 2, (it + 2) % 3);
        CP_COMMIT();

        const char* stg = (const char*)sm + s * STAGE_BYTES;
        const uint4* Bp = (const uint4*)(stg + A_BYTES + wn * 2048 + lane * 16);
        const u32 aS = sm0 + (u32)(s * STAGE_BYTES) + aoff;
#pragma unroll
        for (int ks = 0; ks < 2; ks++) {
            uint4 bc0 = Bp[ks * 64];
            uint4 bc1 = Bp[ks * 64 + 32];
#pragma unroll
            for (int i = 0; i < 4; i++) {
                u32 a0, a1, a2, a3;
                ldsm4(a0, a1, a2, a3, aS + i * 1280 + ks * 32);
                mma_f16(acc[i][0][0], acc[i][0][1], acc[i][0][2], acc[i][0][3],
                        a0, a1, a2, a3, bc0.x, bc0.y);
                mma_f16(acc[i][1][0], acc[i][1][1], acc[i][1][2], acc[i][1][3],
                        a0, a1, a2, a3, bc0.z, bc0.w);
                mma_f16(acc[i][2][0], acc[i][2][1], acc[i][2][2], acc[i][2][3],
                        a0, a1, a2, a3, bc1.x, bc1.y);
                mma_f16(acc[i][3][0], acc[i][3][1], acc[i][3][2], acc[i][3][3],
                        a0, a1, a2, a3, bc1.z, bc1.w);
            }
        }
    }
#undef ISSUE

#pragma unroll
    for (int j = 0; j < 4; j++) {
        int nb = nt * 128 + wn * 32 + j * 8 + 2 * tig;
        float bb0 = b1[nb], bb1 = b1[nb + 1];
#pragma unroll
        for (int i = 0; i < 4; i++) {
            int ma = m0 + wm * 64 + i * 16 + g;
            float2* d0 = (float2*)(g_hid + (size_t)ma * 512 + nb);
            float2* d1 = (float2*)(g_hid + (size_t)(ma + 8) * 512 + nb);
            *d0 = make_float2(fmaxf(acc[i][j][0] + bb0, 0.f),
                              fmaxf(acc[i][j][1] + bb1, 0.f));
            *d1 = make_float2(fmaxf(acc[i][j][2] + bb0, 0.f),
                              fmaxf(acc[i][j][3] + bb1, 0.f));
        }
    }
}

/* ============ kernel 2: 1x1 heads, smem-staged A, 16 pixels/block ======= */
__global__ __launch_bounds__(256) void k_heads(const float* __restrict__ cw,
                                               const float* __restrict__ cb,
                                               const float* __restrict__ rw,
                                               const float* __restrict__ rb) {
    __shared__ float4 As[16][128];            /* 32 KB */
    int tid = threadIdx.x;
    int m0 = blockIdx.x * 16;
    /* stage 16 pixel rows (2048 float4) */
    const float4* src = (const float4*)g_hid + (size_t)m0 * 128;
#pragma unroll
    for (int i = 0; i < 8; i++) {
        int idx = i * 256 + tid;
        As[idx >> 7][idx & 127] = src[idx];
    }
    __syncthreads();
    /* 16*45 = 720 dot products */
    for (int item = tid; item < 16 * 45; item += 256) {
        int p = item / 45, n = item - p * 45;
        const float4* w = (const float4*)((n < 9) ? cw + n * 512
                                                  : rw + (n - 9) * 512);
        float4 acc = make_float4(0.f, 0.f, 0.f, 0.f);
#pragma unroll 16
        for (int i = 0; i < 128; i++) {
            float4 av = As[p][i], wv = __ldg(w + i);
            acc.x += av.x * wv.x; acc.y += av.y * wv.y;
            acc.z += av.z * wv.z; acc.w += av.w * wv.w;
        }
        float bias = (n < 9) ? cb[n] : rb[n - 9];
        g_po[(size_t)(m0 + p) * 45 + n] = (acc.x + acc.y) + (acc.z + acc.w) + bias;
    }
}

/* ============ kernel 3: max IoU per (b,g) =============================== */
__global__ void k_maxpg(const float* __restrict__ gtb) {
    int b = blockIdx.x / GG, g = blockIdx.x % GG;
    int tid = threadIdx.x;
    float gx1 = __fmul_rn(gtb[(b * GG + g) * 4 + 0], 0.03125f);
    float gy1 = __fmul_rn(gtb[(b * GG + g) * 4 + 1], 0.03125f);
    float gx2 = __fmul_rn(gtb[(b * GG + g) * 4 + 2], 0.03125f);
    float gy2 = __fmul_rn(gtb[(b * GG + g) * 4 + 3], 0.03125f);
    float areaG = __fmul_rn(__fsub_rn(gx2, gx1), __fsub_rn(gy2, gy1));
    float mx = 0.f;
    for (int n = tid; n < NN; n += 256) {
        float x1, y1, x2, y2, aA;
        anchor_of(n, x1, y1, x2, y2, aA);
        mx = fmaxf(mx, iou_f(x1, y1, x2, y2, aA, gx1, gy1, gx2, gy2, areaG));
    }
    __shared__ float red[256];
    red[tid] = mx;
    __syncthreads();
    for (int s = 128; s > 0; s >>= 1) {
        if (tid < s) red[tid] = fmaxf(red[tid], red[tid + s]);
        __syncthreads();
    }
    if (tid == 0) g_maxpg[blockIdx.x] = red[0];
}

/* ============ kernel 4: assign + losses + proposals ===================== */
__global__ void k_loss(const float* __restrict__ gtb, float* __restrict__ out) {
    __shared__ float sg[GG][4], sArea[GG], sMpg[GG];
    __shared__ float redc[256], redr[256];
    int tid = threadIdx.x;
    int b = blockIdx.x / 36;
    int gid = blockIdx.x * 256 + tid;
    int n = gid - b * NN;

    if (tid < 80) sg[tid >> 2][tid & 3] = __fmul_rn(gtb[b * 80 + tid], 0.03125f);
    __syncthreads();
    if (tid < GG) {
        sArea[tid] = __fmul_rn(__fsub_rn(sg[tid][2], sg[tid][0]),
                               __fsub_rn(sg[tid][3], sg[tid][1]));
        sMpg[tid] = g_maxpg[b * GG + tid];
    }
    __syncthreads();

    float x1, y1, x2, y2, aA;
    anchor_of(n, x1, y1, x2, y2, aA);

    float maxi = -1e30f; int gi = 0; bool pos = false;
#pragma unroll
    for (int g = 0; g < GG; g++) {
        float io = iou_f(x1, y1, x2, y2, aA, sg[g][0], sg[g][1], sg[g][2], sg[g][3],
                         sArea[g]);
        if (io > 0.7f) pos = true;
        if (io == sMpg[g] && sMpg[g] > EPSF) pos = true;
        if (io > maxi) { maxi = io; gi = g; }
    }
    bool neg = (maxi < 0.3f) && !pos;
    float posf = pos ? 1.f : 0.f;

    float gx1 = sg[gi][0], gy1 = sg[gi][1], gx2 = sg[gi][2], gy2 = sg[gi][3];

    float acx = (x1 + x2) * 0.5f, acy = (y1 + y2) * 0.5f;
    float aw = x2 - x1, ah = y2 - y1;
    float gcx = (gx1 + gx2) * 0.5f, gcy = (gy1 + gy2) * 0.5f;
    float gw = gx2 - gx1, gh = gy2 - gy1;
    float t0 = (gcx - acx) / (aw + EPSF);
    float t1 = (gcy - acy) / (ah + EPSF);
    float t2 = logf((gw + EPSF) / (aw + EPSF));
    float t3 = logf((gh + EPSF) / (ah + EPSF));

    int cell = n / 9; int a = n - cell * 9;
    size_t pb = (size_t)(b * 1024 + cell) * 45;
    float conf = g_po[pb + a];
    float o0 = g_po[pb + 9 + a * 4 + 0];
    float o1 = g_po[pb + 9 + a * 4 + 1];
    float o2 = g_po[pb + 9 + a * 4 + 2];
    float o3 = g_po[pb + 9 + a * 4 + 3];

    float clsv = pos ? softplusf(-conf) : (neg ? softplusf(conf) : 0.f);
    float regv = 0.f;
    if (pos) {
        float d0 = o0 - t0, d1 = o1 - t1, d2 = o2 - t2, d3 = o3 - t3;
        float s0 = fabsf(d0) < 1.f ? 0.5f * d0 * d0 : fabsf(d0) - 0.5f;
        float s1 = fabsf(d1) < 1.f ? 0.5f * d1 * d1 : fabsf(d1) - 0.5f;
        float s2 = fabsf(d2) < 1.f ? 0.5f * d2 * d2 : fabsf(d2) - 0.5f;
        float s3 = fabsf(d3) < 1.f ? 0.5f * d3 * d3 : fabsf(d3) - 0.5f;
        regv = s0 + s1 + s2 + s3;
    }

    float pcx = acx + o0 * aw, pcy = acy + o1 * ah;
    float pw = aw * expf(o2), ph = ah * expf(o3);
    float* pr = out + 1 + (size_t)gid * 4;
    pr[0] = (pcx - pw * 0.5f) * posf;
    pr[1] = (pcy - ph * 0.5f) * posf;
    pr[2] = (pcx + pw * 0.5f) * posf;
    pr[3] = (pcy + ph * 0.5f) * posf;
    out[1 + (size_t)BB * NN * 4 + gid] = posf;

    redc[tid] = clsv; redr[tid] = regv;
    __syncthreads();
    for (int s = 128; s > 0; s >>= 1) {
        if (tid < s) { redc[tid] += redc[tid + s]; redr[tid] += redr[tid + s]; }
        __syncthreads();
    }
    if (tid == 0) { g_clsp[blockIdx.x] = redc[0]; g_regp[blockIdx.x] = redr[0]; }
}

/* ============ kernel 5: finalize scalar loss ============================ */
__global__ void k_fin(float* __restrict__ out) {
    float c = 0.f, r = 0.f;
    for (int i = 0; i < 144; i++) { c += g_clsp[i]; r += g_regp[i]; }
    out[0] = (c + 5.f * r) * 0.25f;
}

/* ============ launch ==================================================== */
extern "C" void kernel_launch(void* const* d_in, const int* in_sizes, int n_in,
                              void* d_out, int out_size) {
    const float* fm  = (const float*)d_in[0];
    const float* gtb = (const float*)d_in[1];
    const float* w1  = (const float*)d_in[3];
    const float* b1  = (const float*)d_in[4];
    const float* cw  = (const float*)d_in[5];
    const float* cb  = (const float*)d_in[6];
    const float* rw  = (const float*)d_in[7];
    const float* rb  = (const float*)d_in[8];
    float* out = (float*)d_out;

    cudaFuncSetAttribute(k_convmma, cudaFuncAttributeMaxDynamicSharedMemorySize,
                         SMEM_BYTES);

    k_fmt<<<dim3(32, 64, 4), dim3(32, 8)>>>(fm);
    k_wpack<<<dim3(64, 16), 256>>>(w1);
    k_convmma<<<dim3(32, 4), 256, SMEM_BYTES>>>(b1);
    k_heads<<<256, 256>>>(cw, cb, rw, rb);
    k_maxpg<<<BB * GG, 256>>>(gtb);
    k_loss<<<144, 256>>>(gtb, out);
    k_fin<<<1, 1>>>(out);
}

// round 15
// speedup vs baseline: 1.1150x; 1.1150x over previous
#include <cuda_runtime.h>
#include <cuda_fp16.h>
#include <cstdint>

typedef unsigned int u32;

#define BB 4
#define HID 512
#define GG 20
#define NN (32*32*9)
#define MM (4*32*32)
#define KK (2048*9)
#define KTILES 576              /* 9 taps x 64 channel-chunks of 32 */
#define A_BYTES 10240           /* 128 rows * 80B (32 halves + 8 pad) */
#define B_BYTES 8192            /* 128 n * 32 k * 2B, fragment-packed */
#define STAGE_BYTES (A_BYTES + B_BYTES)   /* 18432 */
#define SMEM_BYTES (3*STAGE_BYTES)        /* 55296 */
#define NFMT (MM*2048)          /* halves: 8388608  */
#define NWF (512*18432)         /* halves: 9437184  */
#define WS 516                  /* k_heads weight smem row stride (floats) */
#define HEADS_SMEM (45*WS*4)    /* 92880 bytes */
#define EPSF 1e-8f

/* ---------------- scratch (static device globals; no allocation) ------- */
__device__ uint4 g_fmt4[NFMT/8];              /* pixel-major fp16 input [pix][c] */
__device__ uint4 g_wf4[NWF/8];                /* fragment-packed fp16 weights    */
__device__ float g_hid[MM * HID];             /* relu(conv1) pixel-major         */
__device__ float g_po[MM * 45];               /* per pixel: 9 conf + 36 reg      */
__device__ float g_maxpg[BB * GG];
__device__ float g_clsp[144];
__device__ float g_regp[144];

/* ---------------- helpers ---------------------------------------------- */
__device__ __forceinline__ u32 s2u(const void* p) {
    u32 a;
    asm("{ .reg .u64 t; cvta.to.shared.u64 t, %1; cvt.u32.u64 %0, t; }" : "=r"(a) : "l"(p));
    return a;
}
__device__ __forceinline__ void cpa16(u32 dst, const void* src) {
    asm volatile("cp.async.cg.shared.global [%0], [%1], 16;" :: "r"(dst), "l"(src));
}
__device__ __forceinline__ void cpa16z(u32 dst, const void* src, int srcsize) {
    asm volatile("cp.async.cg.shared.global [%0], [%1], 16, %2;"
                 :: "r"(dst), "l"(src), "r"(srcsize));
}
#define CP_COMMIT() asm volatile("cp.async.commit_group;" ::: "memory")
#define CP_WAIT1()  asm volatile("cp.async.wait_group 1;" ::: "memory")

__device__ __forceinline__ void ldsm4(u32& r0, u32& r1, u32& r2, u32& r3, u32 addr) {
    asm volatile("ldmatrix.sync.aligned.m8n8.x4.shared.b16 {%0,%1,%2,%3}, [%4];"
                 : "=r"(r0), "=r"(r1), "=r"(r2), "=r"(r3) : "r"(addr));
}
__device__ __forceinline__ void mma_f16(float& d0, float& d1, float& d2, float& d3,
                                        u32 a0, u32 a1, u32 a2, u32 a3,
                                        u32 b0, u32 b1) {
    asm volatile(
        "mma.sync.aligned.m16n8k16.row.col.f32.f16.f16.f32 "
        "{%0,%1,%2,%3}, {%4,%5,%6,%7}, {%8,%9}, {%0,%1,%2,%3};"
        : "+f"(d0), "+f"(d1), "+f"(d2), "+f"(d3)
        : "r"(a0), "r"(a1), "r"(a2), "r"(a3), "r"(b0), "r"(b1));
}
__device__ __forceinline__ float softplusf(float z) {
    return fmaxf(z, 0.f) + log1pf(expf(-fabsf(z)));
}
__device__ __forceinline__ void anchor_of(int n, float& x1, float& y1, float& x2,
                                          float& y2, float& areaA) {
    int cell = n / 9;  int a = n - cell * 9;
    int yI = cell >> 5, xI = cell & 31;
    int s = a / 3;     int r = a - s * 3;
    float aw = (float)(2 * (s + 1));
    float ah = __fmul_rn(aw, 0.5f + 0.5f * (float)r);
    float xc = (float)xI + 0.5f, yc = (float)yI + 0.5f;
    float hx = __fmul_rn(0.5f, aw), hy = __fmul_rn(0.5f, ah);
    x1 = fminf(fmaxf(__fsub_rn(xc, hx), 0.f), 32.f);
    y1 = fminf(fmaxf(__fsub_rn(yc, hy), 0.f), 32.f);
    x2 = fminf(fmaxf(__fadd_rn(xc, hx), 0.f), 32.f);
    y2 = fminf(fmaxf(__fadd_rn(yc, hy), 0.f), 32.f);
    areaA = __fmul_rn(__fsub_rn(x2, x1), __fsub_rn(y2, y1));
}
__device__ __forceinline__ float iou_f(float ax1, float ay1, float ax2, float ay2,
                                       float areaA, float gx1, float gy1, float gx2,
                                       float gy2, float areaG) {
    float lx = fmaxf(ax1, gx1), ly = fmaxf(ay1, gy1);
    float rx = fminf(ax2, gx2), ry = fminf(ay2, gy2);
    float iw = fmaxf(__fsub_rn(rx, lx), 0.f);
    float ih = fmaxf(__fsub_rn(ry, ly), 0.f);
    float inter = __fmul_rn(iw, ih);
    float den = __fadd_rn(__fsub_rn(__fadd_rn(areaA, areaG), inter), EPSF);
    return __fdiv_rn(inter, den);
}

/* ============ kernel 0a: transpose fm to pixel-major fp16 =============== */
__global__ __launch_bounds__(256) void k_fmt(const float* __restrict__ fm) {
    __shared__ float t[32][33];
    int pb = blockIdx.x * 32, cb = blockIdx.y * 32, b = blockIdx.z;
    int tx = threadIdx.x, ty = threadIdx.y;
    __half* gf = (__half*)g_fmt4;
#pragma unroll
    for (int i = ty; i < 32; i += 8)
        t[i][tx] = __ldg(fm + ((size_t)(b * 2048 + cb + i) << 10) + pb + tx);
    __syncthreads();
#pragma unroll
    for (int i = ty; i < 32; i += 8)
        gf[(((size_t)(b * 1024 + pb + i)) << 11) + cb + tx] = __float2half(t[tx][i]);
}

/* ============ kernel 0b: repack weights into fp16 mma-fragment order ==== */
__global__ __launch_bounds__(256) void k_wpack(const float* __restrict__ w1) {
    __shared__ float s[32][289];
    int cb = blockIdx.x;
    int nb = blockIdx.y;
    int n0b = nb * 32;
    int nt = nb >> 2, wn = nb & 3;
    int tid = threadIdx.x;
    __half* gw = (__half*)g_wf4;
    for (int idx = tid; idx < 32 * 288; idx += 256) {
        int r = idx / 288, cc = idx - r * 288;
        s[r][cc] = __ldg(w1 + (size_t)(n0b + r) * KK + cb * 288 + cc);
    }
    __syncthreads();
    for (int t = 0; t < 9; t++) {
        size_t base = ((size_t)(nt * 576 + t * 64 + cb)) * 4096 + wn * 1024;
#pragma unroll
        for (int q = 0; q < 4; q++) {
            int o = q * 256 + tid;
            int h8 = o & 7, lane = (o >> 3) & 31;
            int chunk = (o >> 8) & 1, ks = o >> 9;
            int j = chunk * 2 + (h8 >> 2);
            int r = (h8 >> 1) & 1, hh = h8 & 1;
            int g = lane >> 2, tig = lane & 3;
            int nloc = j * 8 + g;
            int klocal = ks * 16 + r * 8 + 2 * tig + hh;
            gw[base + o] = __float2half(s[nloc][klocal * 9 + t]);
        }
    }
}

/* ============ kernel 1: conv1, fp16 HMMA + ldmatrix, cp.async pipeline == */
__global__ __launch_bounds__(256, 1) void k_convmma(const float* __restrict__ b1) {
    extern __shared__ float sm[];
    const u32 sm0 = s2u(sm);
    const int tid = threadIdx.x;
    const int lane = tid & 31, wid = tid >> 5;
    const int g = lane >> 2, tig = lane & 3;
    const int wm = wid >> 2, wn = wid & 3;
    const int m0 = blockIdx.x * 128;
    const int nt = blockIdx.y;

    const int pp = tid >> 1, hseg = tid & 1;
    const int mp = m0 + pp;
    const int bbp = mp >> 10, yp = (mp >> 5) & 31, xp = mp & 31;

    const u32 aoff = (u32)((wm * 64 + (lane & 7) + ((lane >> 3) & 1) * 8) * 80
                           + ((lane >> 4) & 1) * 16);

    float acc[4][4][4];
#pragma unroll
    for (int i = 0; i < 4; i++)
#pragma unroll
        for (int j = 0; j < 4; j++)
#pragma unroll
            for (int c = 0; c < 4; c++) acc[i][j][c] = 0.f;

#define ISSUE(it, s) do {                                                      \
        int tap = (it) >> 6;                                                   \
        int c0 = ((it) & 63) << 5;                                             \
        u32 aB = sm0 + (u32)((s) * STAGE_BYTES);                               \
        {                                                                      \
            const uint4* srcB = g_wf4 + (size_t)(nt * 576 + (it)) * 512        \
                                + tid * 2;                                     \
            u32 dB = aB + A_BYTES + (u32)tid * 32;                             \
            cpa16(dB, srcB); cpa16(dB + 16, srcB + 1);                         \
        }                                                                      \
        {                                                                      \
            int dy = tap / 3 - 1, dx = tap - (tap / 3) * 3 - 1;                \
            int yy = yp + dy, xx = xp + dx;                                    \
            int vs = ((unsigned)yy < 32u && (unsigned)xx < 32u) ? 16 : 0;      \
            const uint4* srcA = vs ? g_fmt4 +                                  \
                ((size_t)((bbp << 10) + (yy << 5) + xx)) * 256                 \
                + (c0 >> 3) + hseg * 2 : g_fmt4;                               \
            u32 dA = aB + (u32)(pp * 80 + hseg * 32);                          \
            cpa16z(dA, srcA, vs); cpa16z(dA + 16, srcA + 1, vs);               \
        }                                                                      \
    } while (0)

    ISSUE(0, 0); CP_COMMIT();
    ISSUE(1, 1); CP_COMMIT();

    for (int it = 0; it < KTILES; it++) {
        CP_WAIT1();
        __syncthreads();
        const int s = it % 3;
        if (it + 2 < KTILES) ISSUE(it + 2, (it + 2) % 3);
        CP_COMMIT();

        const char* stg = (const char*)sm + s * STAGE_BYTES;
        const uint4* Bp = (const uint4*)(stg + A_BYTES + wn * 2048 + lane * 16);
        const u32 aS = sm0 + (u32)(s * STAGE_BYTES) + aoff;
#pragma unroll
        for (int ks = 0; ks < 2; ks++) {
            uint4 bc0 = Bp[ks * 64];
            uint4 bc1 = Bp[ks * 64 + 32];
#pragma unroll
            for (int i = 0; i < 4; i++) {
                u32 a0, a1, a2, a3;
                ldsm4(a0, a1, a2, a3, aS + i * 1280 + ks * 32);
                mma_f16(acc[i][0][0], acc[i][0][1], acc[i][0][2], acc[i][0][3],
                        a0, a1, a2, a3, bc0.x, bc0.y);
                mma_f16(acc[i][1][0], acc[i][1][1], acc[i][1][2], acc[i][1][3],
                        a0, a1, a2, a3, bc0.z, bc0.w);
                mma_f16(acc[i][2][0], acc[i][2][1], acc[i][2][2], acc[i][2][3],
                        a0, a1, a2, a3, bc1.x, bc1.y);
                mma_f16(acc[i][3][0], acc[i][3][1], acc[i][3][2], acc[i][3][3],
                        a0, a1, a2, a3, bc1.z, bc1.w);
            }
        }
    }
#undef ISSUE

#pragma unroll
    for (int j = 0; j < 4; j++) {
        int nb = nt * 128 + wn * 32 + j * 8 + 2 * tig;
        float bb0 = b1[nb], bb1 = b1[nb + 1];
#pragma unroll
        for (int i = 0; i < 4; i++) {
            int ma = m0 + wm * 64 + i * 16 + g;
            float2* d0 = (float2*)(g_hid + (size_t)ma * 512 + nb);
            float2* d1 = (float2*)(g_hid + (size_t)(ma + 8) * 512 + nb);
            *d0 = make_float2(fmaxf(acc[i][j][0] + bb0, 0.f),
                              fmaxf(acc[i][j][1] + bb1, 0.f));
            *d1 = make_float2(fmaxf(acc[i][j][2] + bb0, 0.f),
                              fmaxf(acc[i][j][3] + bb1, 0.f));
        }
    }
}

/* ============ kernel 2: 1x1 heads, weight-stationary in smem ============ */
/* block = 32 pixels, grid 128. Weights staged once: 45 rows, stride WS.   */
/* Thread -> (p, n). A reads broadcast within warp; W LDS conflict-free.   */
__global__ __launch_bounds__(256) void k_heads(const float* __restrict__ cw,
                                               const float* __restrict__ cb,
                                               const float* __restrict__ rw,
                                               const float* __restrict__ rb) {
    extern __shared__ float Ws[];             /* [45][WS] */
    int tid = threadIdx.x;
    int m0 = blockIdx.x * 32;
    /* stage all 45 weight rows (coalesced float4 loads) */
    for (int idx = tid; idx < 45 * 128; idx += 256) {
        int n = idx >> 7, i = idx & 127;
        const float4* src = (const float4*)((n < 9) ? cw + n * 512
                                                    : rw + (n - 9) * 512);
        *(float4*)(Ws + n * WS + i * 4) = __ldg(src + i);
    }
    __syncthreads();

    /* 32*45 = 1440 dot products, 256 threads -> 5-6 each */
    for (int item = tid; item < 32 * 45; item += 256) {
        int p = item / 45, n = item - p * 45;
        const float4* a = (const float4*)(g_hid + (size_t)(m0 + p) * 512);
        const float4* w = (const float4*)(Ws + n * WS);
        float4 acc = make_float4(0.f, 0.f, 0.f, 0.f);
#pragma unroll 16
        for (int i = 0; i < 128; i++) {
            float4 av = __ldg(a + i), wv = w[i];
            acc.x += av.x * wv.x; acc.y += av.y * wv.y;
            acc.z += av.z * wv.z; acc.w += av.w * wv.w;
        }
        float bias = (n < 9) ? cb[n] : rb[n - 9];
        g_po[(size_t)(m0 + p) * 45 + n] = (acc.x + acc.y) + (acc.z + acc.w) + bias;
    }
}

/* ============ kernel 3: max IoU per (b,g) =============================== */
__global__ void k_maxpg(const float* __restrict__ gtb) {
    int b = blockIdx.x / GG, g = blockIdx.x % GG;
    int tid = threadIdx.x;
    float gx1 = __fmul_rn(gtb[(b * GG + g) * 4 + 0], 0.03125f);
    float gy1 = __fmul_rn(gtb[(b * GG + g) * 4 + 1], 0.03125f);
    float gx2 = __fmul_rn(gtb[(b * GG + g) * 4 + 2], 0.03125f);
    float gy2 = __fmul_rn(gtb[(b * GG + g) * 4 + 3], 0.03125f);
    float areaG = __fmul_rn(__fsub_rn(gx2, gx1), __fsub_rn(gy2, gy1));
    float mx = 0.f;
    for (int n = tid; n < NN; n += 256) {
        float x1, y1, x2, y2, aA;
        anchor_of(n, x1, y1, x2, y2, aA);
        mx = fmaxf(mx, iou_f(x1, y1, x2, y2, aA, gx1, gy1, gx2, gy2, areaG));
    }
    __shared__ float red[256];
    red[tid] = mx;
    __syncthreads();
    for (int s = 128; s > 0; s >>= 1) {
        if (tid < s) red[tid] = fmaxf(red[tid], red[tid + s]);
        __syncthreads();
    }
    if (tid == 0) g_maxpg[blockIdx.x] = red[0];
}

/* ============ kernel 4: assign + losses + proposals ===================== */
__global__ void k_loss(const float* __restrict__ gtb, float* __restrict__ out) {
    __shared__ float sg[GG][4], sArea[GG], sMpg[GG];
    __shared__ float redc[256], redr[256];
    int tid = threadIdx.x;
    int b = blockIdx.x / 36;
    int gid = blockIdx.x * 256 + tid;
    int n = gid - b * NN;

    if (tid < 80) sg[tid >> 2][tid & 3] = __fmul_rn(gtb[b * 80 + tid], 0.03125f);
    __syncthreads();
    if (tid < GG) {
        sArea[tid] = __fmul_rn(__fsub_rn(sg[tid][2], sg[tid][0]),
                               __fsub_rn(sg[tid][3], sg[tid][1]));
        sMpg[tid] = g_maxpg[b * GG + tid];
    }
    __syncthreads();

    float x1, y1, x2, y2, aA;
    anchor_of(n, x1, y1, x2, y2, aA);

    float maxi = -1e30f; int gi = 0; bool pos = false;
#pragma unroll
    for (int g = 0; g < GG; g++) {
        float io = iou_f(x1, y1, x2, y2, aA, sg[g][0], sg[g][1], sg[g][2], sg[g][3],
                         sArea[g]);
        if (io > 0.7f) pos = true;
        if (io == sMpg[g] && sMpg[g] > EPSF) pos = true;
        if (io > maxi) { maxi = io; gi = g; }
    }
    bool neg = (maxi < 0.3f) && !pos;
    float posf = pos ? 1.f : 0.f;

    float gx1 = sg[gi][0], gy1 = sg[gi][1], gx2 = sg[gi][2], gy2 = sg[gi][3];

    float acx = (x1 + x2) * 0.5f, acy = (y1 + y2) * 0.5f;
    float aw = x2 - x1, ah = y2 - y1;
    float gcx = (gx1 + gx2) * 0.5f, gcy = (gy1 + gy2) * 0.5f;
    float gw = gx2 - gx1, gh = gy2 - gy1;
    float t0 = (gcx - acx) / (aw + EPSF);
    float t1 = (gcy - acy) / (ah + EPSF);
    float t2 = logf((gw + EPSF) / (aw + EPSF));
    float t3 = logf((gh + EPSF) / (ah + EPSF));

    int cell = n / 9; int a = n - cell * 9;
    size_t pb = (size_t)(b * 1024 + cell) * 45;
    float conf = g_po[pb + a];
    float o0 = g_po[pb + 9 + a * 4 + 0];
    float o1 = g_po[pb + 9 + a * 4 + 1];
    float o2 = g_po[pb + 9 + a * 4 + 2];
    float o3 = g_po[pb + 9 + a * 4 + 3];

    float clsv = pos ? softplusf(-conf) : (neg ? softplusf(conf) : 0.f);
    float regv = 0.f;
    if (pos) {
        float d0 = o0 - t0, d1 = o1 - t1, d2 = o2 - t2, d3 = o3 - t3;
        float s0 = fabsf(d0) < 1.f ? 0.5f * d0 * d0 : fabsf(d0) - 0.5f;
        float s1 = fabsf(d1) < 1.f ? 0.5f * d1 * d1 : fabsf(d1) - 0.5f;
        float s2 = fabsf(d2) < 1.f ? 0.5f * d2 * d2 : fabsf(d2) - 0.5f;
        float s3 = fabsf(d3) < 1.f ? 0.5f * d3 * d3 : fabsf(d3) - 0.5f;
        regv = s0 + s1 + s2 + s3;
    }

    float pcx = acx + o0 * aw, pcy = acy + o1 * ah;
    float pw = aw * expf(o2), ph = ah * expf(o3);
    float* pr = out + 1 + (size_t)gid * 4;
    pr[0] = (pcx - pw * 0.5f) * posf;
    pr[1] = (pcy - ph * 0.5f) * posf;
    pr[2] = (pcx + pw * 0.5f) * posf;
    pr[3] = (pcy + ph * 0.5f) * posf;
    out[1 + (size_t)BB * NN * 4 + gid] = posf;

    redc[tid] = clsv; redr[tid] = regv;
    __syncthreads();
    for (int s = 128; s > 0; s >>= 1) {
        if (tid < s) { redc[tid] += redc[tid + s]; redr[tid] += redr[tid + s]; }
        __syncthreads();
    }
    if (tid == 0) { g_clsp[blockIdx.x] = redc[0]; g_regp[blockIdx.x] = redr[0]; }
}

/* ============ kernel 5: finalize scalar loss ============================ */
__global__ void k_fin(float* __restrict__ out) {
    float c = 0.f, r = 0.f;
    for (int i = 0; i < 144; i++) { c += g_clsp[i]; r += g_regp[i]; }
    out[0] = (c + 5.f * r) * 0.25f;
}

/* ============ launch ==================================================== */
extern "C" void kernel_launch(void* const* d_in, const int* in_sizes, int n_in,
                              void* d_out, int out_size) {
    const float* fm  = (const float*)d_in[0];
    const float* gtb = (const float*)d_in[1];
    const float* w1  = (const float*)d_in[3];
    const float* b1  = (const float*)d_in[4];
    const float* cw  = (const float*)d_in[5];
    const float* cb  = (const float*)d_in[6];
    const float* rw  = (const float*)d_in[7];
    const float* rb  = (const float*)d_in[8];
    float* out = (float*)d_out;

    cudaFuncSetAttribute(k_convmma, cudaFuncAttributeMaxDynamicSharedMemorySize,
                         SMEM_BYTES);
    cudaFuncSetAttribute(k_heads, cudaFuncAttributeMaxDynamicSharedMemorySize,
                         HEADS_SMEM);

    k_fmt<<<dim3(32, 64, 4), dim3(32, 8)>>>(fm);
    k_wpack<<<dim3(64, 16), 256>>>(w1);
    k_convmma<<<dim3(32, 4), 256, SMEM_BYTES>>>(b1);
    k_heads<<<128, 256, HEADS_SMEM>>>(cw, cb, rw, rb);
    k_maxpg<<<BB * GG, 256>>>(gtb);
    k_loss<<<144, 256>>>(gtb, out);
    k_fin<<<1, 1>>>(out);
}

// round 16
// speedup vs baseline: 1.2054x; 1.0810x over previous
#include <cuda_runtime.h>
#include <cuda_fp16.h>
#include <cstdint>

typedef unsigned int u32;

#define BB 4
#define HID 512
#define GG 20
#define NN (32*32*9)
#define MM (4*32*32)
#define KK (2048*9)
#define KTILES 576              /* 9 taps x 64 channel-chunks of 32 */
#define KSPL 2
#define KHALF (KTILES/KSPL)     /* 288 */
#define A_BYTES 10240           /* 128 rows * 80B (32 halves + 8 pad) */
#define B_BYTES 8192            /* 128 n * 32 k * 2B, fragment-packed */
#define STAGE_BYTES (A_BYTES + B_BYTES)   /* 18432 */
#define SMEM_BYTES (3*STAGE_BYTES)        /* 55296 */
#define NFMT (MM*2048)          /* halves: 8388608  */
#define NWF (512*18432)         /* halves: 9437184  */
#define EPSF 1e-8f

/* ---------------- scratch (static device globals; no allocation) ------- */
__device__ uint4 g_fmt4[NFMT/8];              /* pixel-major fp16 input [pix][c] */
__device__ uint4 g_wf4[NWF/8];                /* fragment-packed fp16 weights    */
__device__ float g_part[KSPL * MM * HID];     /* conv K-split partials           */
__device__ float g_hid[MM * HID];             /* relu(conv1) pixel-major         */
__device__ float g_po[MM * 45];               /* per pixel: 9 conf + 36 reg      */
__device__ float g_maxpg[BB * GG];
__device__ float g_clsp[144];
__device__ float g_regp[144];

/* ---------------- helpers ---------------------------------------------- */
__device__ __forceinline__ u32 s2u(const void* p) {
    u32 a;
    asm("{ .reg .u64 t; cvta.to.shared.u64 t, %1; cvt.u32.u64 %0, t; }" : "=r"(a) : "l"(p));
    return a;
}
__device__ __forceinline__ void cpa16(u32 dst, const void* src) {
    asm volatile("cp.async.cg.shared.global [%0], [%1], 16;" :: "r"(dst), "l"(src));
}
__device__ __forceinline__ void cpa16z(u32 dst, const void* src, int srcsize) {
    asm volatile("cp.async.cg.shared.global [%0], [%1], 16, %2;"
                 :: "r"(dst), "l"(src), "r"(srcsize));
}
#define CP_COMMIT() asm volatile("cp.async.commit_group;" ::: "memory")
#define CP_WAIT1()  asm volatile("cp.async.wait_group 1;" ::: "memory")

__device__ __forceinline__ void ldsm4(u32& r0, u32& r1, u32& r2, u32& r3, u32 addr) {
    asm volatile("ldmatrix.sync.aligned.m8n8.x4.shared.b16 {%0,%1,%2,%3}, [%4];"
                 : "=r"(r0), "=r"(r1), "=r"(r2), "=r"(r3) : "r"(addr));
}
__device__ __forceinline__ void mma_f16(float& d0, float& d1, float& d2, float& d3,
                                        u32 a0, u32 a1, u32 a2, u32 a3,
                                        u32 b0, u32 b1) {
    asm volatile(
        "mma.sync.aligned.m16n8k16.row.col.f32.f16.f16.f32 "
        "{%0,%1,%2,%3}, {%4,%5,%6,%7}, {%8,%9}, {%0,%1,%2,%3};"
        : "+f"(d0), "+f"(d1), "+f"(d2), "+f"(d3)
        : "r"(a0), "r"(a1), "r"(a2), "r"(a3), "r"(b0), "r"(b1));
}
__device__ __forceinline__ float softplusf(float z) {
    return fmaxf(z, 0.f) + log1pf(expf(-fabsf(z)));
}
__device__ __forceinline__ void anchor_of(int n, float& x1, float& y1, float& x2,
                                          float& y2, float& areaA) {
    int cell = n / 9;  int a = n - cell * 9;
    int yI = cell >> 5, xI = cell & 31;
    int s = a / 3;     int r = a - s * 3;
    float aw = (float)(2 * (s + 1));
    float ah = __fmul_rn(aw, 0.5f + 0.5f * (float)r);
    float xc = (float)xI + 0.5f, yc = (float)yI + 0.5f;
    float hx = __fmul_rn(0.5f, aw), hy = __fmul_rn(0.5f, ah);
    x1 = fminf(fmaxf(__fsub_rn(xc, hx), 0.f), 32.f);
    y1 = fminf(fmaxf(__fsub_rn(yc, hy), 0.f), 32.f);
    x2 = fminf(fmaxf(__fadd_rn(xc, hx), 0.f), 32.f);
    y2 = fminf(fmaxf(__fadd_rn(yc, hy), 0.f), 32.f);
    areaA = __fmul_rn(__fsub_rn(x2, x1), __fsub_rn(y2, y1));
}
__device__ __forceinline__ float iou_f(float ax1, float ay1, float ax2, float ay2,
                                       float areaA, float gx1, float gy1, float gx2,
                                       float gy2, float areaG) {
    float lx = fmaxf(ax1, gx1), ly = fmaxf(ay1, gy1);
    float rx = fminf(ax2, gx2), ry = fminf(ay2, gy2);
    float iw = fmaxf(__fsub_rn(rx, lx), 0.f);
    float ih = fmaxf(__fsub_rn(ry, ly), 0.f);
    float inter = __fmul_rn(iw, ih);
    float den = __fadd_rn(__fsub_rn(__fadd_rn(areaA, areaG), inter), EPSF);
    return __fdiv_rn(inter, den);
}

/* ============ kernel 0a: transpose fm to pixel-major fp16 =============== */
__global__ __launch_bounds__(256) void k_fmt(const float* __restrict__ fm) {
    __shared__ float t[32][33];
    int pb = blockIdx.x * 32, cb = blockIdx.y * 32, b = blockIdx.z;
    int tx = threadIdx.x, ty = threadIdx.y;
    __half* gf = (__half*)g_fmt4;
#pragma unroll
    for (int i = ty; i < 32; i += 8)
        t[i][tx] = __ldg(fm + ((size_t)(b * 2048 + cb + i) << 10) + pb + tx);
    __syncthreads();
#pragma unroll
    for (int i = ty; i < 32; i += 8)
        gf[(((size_t)(b * 1024 + pb + i)) << 11) + cb + tx] = __float2half(t[tx][i]);
}

/* ============ kernel 0b: repack weights into fp16 mma-fragment order ==== */
__global__ __launch_bounds__(256) void k_wpack(const float* __restrict__ w1) {
    __shared__ float s[32][289];
    int cb = blockIdx.x;
    int nb = blockIdx.y;
    int n0b = nb * 32;
    int nt = nb >> 2, wn = nb & 3;
    int tid = threadIdx.x;
    __half* gw = (__half*)g_wf4;
    for (int idx = tid; idx < 32 * 288; idx += 256) {
        int r = idx / 288, cc = idx - r * 288;
        s[r][cc] = __ldg(w1 + (size_t)(n0b + r) * KK + cb * 288 + cc);
    }
    __syncthreads();
    for (int t = 0; t < 9; t++) {
        size_t base = ((size_t)(nt * 576 + t * 64 + cb)) * 4096 + wn * 1024;
#pragma unroll
        for (int q = 0; q < 4; q++) {
            int o = q * 256 + tid;
            int h8 = o & 7, lane = (o >> 3) & 31;
            int chunk = (o >> 8) & 1, ks = o >> 9;
            int j = chunk * 2 + (h8 >> 2);
            int r = (h8 >> 1) & 1, hh = h8 & 1;
            int g = lane >> 2, tig = lane & 3;
            int nloc = j * 8 + g;
            int klocal = ks * 16 + r * 8 + 2 * tig + hh;
            gw[base + o] = __float2half(s[nloc][klocal * 9 + t]);
        }
    }
}

/* ============ kernel 1: conv1, fp16 HMMA + ldmatrix, K-split 2 ========== */
__global__ __launch_bounds__(256, 2) void k_convmma() {
    extern __shared__ float sm[];
    const u32 sm0 = s2u(sm);
    const int tid = threadIdx.x;
    const int lane = tid & 31, wid = tid >> 5;
    const int g = lane >> 2, tig = lane & 3;
    const int wm = wid >> 2, wn = wid & 3;
    const int m0 = blockIdx.x * 128;
    const int nt = blockIdx.y;
    const int kt = blockIdx.z;
    const int it0 = kt * KHALF;

    const int pp = tid >> 1, hseg = tid & 1;
    const int mp = m0 + pp;
    const int bbp = mp >> 10, yp = (mp >> 5) & 31, xp = mp & 31;

    const u32 aoff = (u32)((wm * 64 + (lane & 7) + ((lane >> 3) & 1) * 8) * 80
                           + ((lane >> 4) & 1) * 16);

    float acc[4][4][4];
#pragma unroll
    for (int i = 0; i < 4; i++)
#pragma unroll
        for (int j = 0; j < 4; j++)
#pragma unroll
            for (int c = 0; c < 4; c++) acc[i][j][c] = 0.f;

#define ISSUE(itg, s) do {                                                     \
        int tap = (itg) >> 6;                                                  \
        int c0 = ((itg) & 63) << 5;                                            \
        u32 aB = sm0 + (u32)((s) * STAGE_BYTES);                               \
        {                                                                      \
            const uint4* srcB = g_wf4 + (size_t)(nt * 576 + (itg)) * 512       \
                                + tid * 2;                                     \
            u32 dB = aB + A_BYTES + (u32)tid * 32;                             \
            cpa16(dB, srcB); cpa16(dB + 16, srcB + 1);                         \
        }                                                                      \
        {                                                                      \
            int dy = tap / 3 - 1, dx = tap - (tap / 3) * 3 - 1;                \
            int yy = yp + dy, xx = xp + dx;                                    \
            int vs = ((unsigned)yy < 32u && (unsigned)xx < 32u) ? 16 : 0;      \
            const uint4* srcA = vs ? g_fmt4 +                                  \
                ((size_t)((bbp << 10) + (yy << 5) + xx)) * 256                 \
                + (c0 >> 3) + hseg * 2 : g_fmt4;                               \
            u32 dA = aB + (u32)(pp * 80 + hseg * 32);                          \
            cpa16z(dA, srcA, vs); cpa16z(dA + 16, srcA + 1, vs);               \
        }                                                                      \
    } while (0)

    ISSUE(it0, 0); CP_COMMIT();
    ISSUE(it0 + 1, 1); CP_COMMIT();

    for (int it = 0; it < KHALF; it++) {
        CP_WAIT1();
        __syncthreads();
        const int s = it % 3;
        if (it + 2 < KHALF) ISSUE(it0 + it + 2, (it + 2) % 3);
        CP_COMMIT();

        const char* stg = (const char*)sm + s * STAGE_BYTES;
        const uint4* Bp = (const uint4*)(stg + A_BYTES + wn * 2048 + lane * 16);
        const u32 aS = sm0 + (u32)(s * STAGE_BYTES) + aoff;
#pragma unroll
        for (int ks = 0; ks < 2; ks++) {
            uint4 bc0 = Bp[ks * 64];
            uint4 bc1 = Bp[ks * 64 + 32];
#pragma unroll
            for (int i = 0; i < 4; i++) {
                u32 a0, a1, a2, a3;
                ldsm4(a0, a1, a2, a3, aS + i * 1280 + ks * 32);
                mma_f16(acc[i][0][0], acc[i][0][1], acc[i][0][2], acc[i][0][3],
                        a0, a1, a2, a3, bc0.x, bc0.y);
                mma_f16(acc[i][1][0], acc[i][1][1], acc[i][1][2], acc[i][1][3],
                        a0, a1, a2, a3, bc0.z, bc0.w);
                mma_f16(acc[i][2][0], acc[i][2][1], acc[i][2][2], acc[i][2][3],
                        a0, a1, a2, a3, bc1.x, bc1.y);
                mma_f16(acc[i][3][0], acc[i][3][1], acc[i][3][2], acc[i][3][3],
                        a0, a1, a2, a3, bc1.z, bc1.w);
            }
        }
    }
#undef ISSUE

    /* ---- epilogue: raw partials -> g_part[kt] ---- */
    float* gp = g_part + (size_t)kt * MM * HID;
#pragma unroll
    for (int j = 0; j < 4; j++) {
        int nb = nt * 128 + wn * 32 + j * 8 + 2 * tig;
#pragma unroll
        for (int i = 0; i < 4; i++) {
            int ma = m0 + wm * 64 + i * 16 + g;
            *(float2*)(gp + (size_t)ma * 512 + nb) =
                make_float2(acc[i][j][0], acc[i][j][1]);
            *(float2*)(gp + (size_t)(ma + 8) * 512 + nb) =
                make_float2(acc[i][j][2], acc[i][j][3]);
        }
    }
}

/* ============ kernel 1b: merge partials + bias + relu =================== */
__global__ __launch_bounds__(256) void k_reduce(const float* __restrict__ b1) {
    int i = blockIdx.x * 256 + threadIdx.x;       /* float4 idx, 524288 total */
    const float4* p = (const float4*)g_part;
    float4 a = p[i], b = p[i + 524288];
    float4 bias = __ldg((const float4*)b1 + (i & 127));
    float4 o;
    o.x = fmaxf(a.x + b.x + bias.x, 0.f);
    o.y = fmaxf(a.y + b.y + bias.y, 0.f);
    o.z = fmaxf(a.z + b.z + bias.z, 0.f);
    o.w = fmaxf(a.w + b.w + bias.w, 0.f);
    ((float4*)g_hid)[i] = o;
}

/* ============ kernel 2: 1x1 heads, warp-per-pixel, A in registers ======= */
__global__ __launch_bounds__(256) void k_heads(const float* __restrict__ cw,
                                               const float* __restrict__ cb,
                                               const float* __restrict__ rw,
                                               const float* __restrict__ rb) {
    int tid = threadIdx.x;
    int lane = tid & 31;
    int p = blockIdx.x * 8 + (tid >> 5);
    const float* a = g_hid + (size_t)p * 512;
    float av[16];
#pragma unroll
    for (int i = 0; i < 16; i++) av[i] = a[lane + 32 * i];

    float acc[45];
#pragma unroll
    for (int n = 0; n < 45; n++) {
        const float* wr = (n < 9) ? cw + n * 512 : rw + (n - 9) * 512;
        float s = 0.f;
#pragma unroll
        for (int i = 0; i < 16; i++) s += av[i] * __ldg(wr + lane + 32 * i);
        acc[n] = s;
    }
#pragma unroll
    for (int off = 16; off > 0; off >>= 1)
#pragma unroll
        for (int n = 0; n < 45; n++)
            acc[n] += __shfl_xor_sync(0xFFFFFFFFu, acc[n], off);

    /* all lanes hold full sums; lanes 0-31 write n=lane, lanes 0-12 also n=32+lane */
    {
        int n = lane;
        float bias = (n < 9) ? __ldg(cb + n) : __ldg(rb + n - 9);
        g_po[(size_t)p * 45 + n] = acc[n] + bias;
    }
    if (lane < 13) {
        int n = 32 + lane;
        float bias = __ldg(rb + n - 9);
        g_po[(size_t)p * 45 + n] = acc[n] + bias;
    }
}

/* ============ kernel 3: max IoU per (b,g) =============================== */
__global__ void k_maxpg(const float* __restrict__ gtb) {
    int b = blockIdx.x / GG, g = blockIdx.x % GG;
    int tid = threadIdx.x;
    float gx1 = __fmul_rn(gtb[(b * GG + g) * 4 + 0], 0.03125f);
    float gy1 = __fmul_rn(gtb[(b * GG + g) * 4 + 1], 0.03125f);
    float gx2 = __fmul_rn(gtb[(b * GG + g) * 4 + 2], 0.03125f);
    float gy2 = __fmul_rn(gtb[(b * GG + g) * 4 + 3], 0.03125f);
    float areaG = __fmul_rn(__fsub_rn(gx2, gx1), __fsub_rn(gy2, gy1));
    float mx = 0.f;
    for (int n = tid; n < NN; n += 256) {
        float x1, y1, x2, y2, aA;
        anchor_of(n, x1, y1, x2, y2, aA);
        mx = fmaxf(mx, iou_f(x1, y1, x2, y2, aA, gx1, gy1, gx2, gy2, areaG));
    }
    __shared__ float red[256];
    red[tid] = mx;
    __syncthreads();
    for (int s = 128; s > 0; s >>= 1) {
        if (tid < s) red[tid] = fmaxf(red[tid], red[tid + s]);
        __syncthreads();
    }
    if (tid == 0) g_maxpg[blockIdx.x] = red[0];
}

/* ============ kernel 4: assign + losses + proposals ===================== */
__global__ void k_loss(const float* __restrict__ gtb, float* __restrict__ out) {
    __shared__ float sg[GG][4], sArea[GG], sMpg[GG];
    __shared__ float redc[256], redr[256];
    int tid = threadIdx.x;
    int b = blockIdx.x / 36;
    int gid = blockIdx.x * 256 + tid;
    int n = gid - b * NN;

    if (tid < 80) sg[tid >> 2][tid & 3] = __fmul_rn(gtb[b * 80 + tid], 0.03125f);
    __syncthreads();
    if (tid < GG) {
        sArea[tid] = __fmul_rn(__fsub_rn(sg[tid][2], sg[tid][0]),
                               __fsub_rn(sg[tid][3], sg[tid][1]));
        sMpg[tid] = g_maxpg[b * GG + tid];
    }
    __syncthreads();

    float x1, y1, x2, y2, aA;
    anchor_of(n, x1, y1, x2, y2, aA);

    float maxi = -1e30f; int gi = 0; bool pos = false;
#pragma unroll
    for (int g = 0; g < GG; g++) {
        float io = iou_f(x1, y1, x2, y2, aA, sg[g][0], sg[g][1], sg[g][2], sg[g][3],
                         sArea[g]);
        if (io > 0.7f) pos = true;
        if (io == sMpg[g] && sMpg[g] > EPSF) pos = true;
        if (io > maxi) { maxi = io; gi = g; }
    }
    bool neg = (maxi < 0.3f) && !pos;
    float posf = pos ? 1.f : 0.f;

    float gx1 = sg[gi][0], gy1 = sg[gi][1], gx2 = sg[gi][2], gy2 = sg[gi][3];

    float acx = (x1 + x2) * 0.5f, acy = (y1 + y2) * 0.5f;
    float aw = x2 - x1, ah = y2 - y1;
    float gcx = (gx1 + gx2) * 0.5f, gcy = (gy1 + gy2) * 0.5f;
    float gw = gx2 - gx1, gh = gy2 - gy1;
    float t0 = (gcx - acx) / (aw + EPSF);
    float t1 = (gcy - acy) / (ah + EPSF);
    float t2 = logf((gw + EPSF) / (aw + EPSF));
    float t3 = logf((gh + EPSF) / (ah + EPSF));

    int cell = n / 9; int a = n - cell * 9;
    size_t pb = (size_t)(b * 1024 + cell) * 45;
    float conf = g_po[pb + a];
    float o0 = g_po[pb + 9 + a * 4 + 0];
    float o1 = g_po[pb + 9 + a * 4 + 1];
    float o2 = g_po[pb + 9 + a * 4 + 2];
    float o3 = g_po[pb + 9 + a * 4 + 3];

    float clsv = pos ? softplusf(-conf) : (neg ? softplusf(conf) : 0.f);
    float regv = 0.f;
    if (pos) {
        float d0 = o0 - t0, d1 = o1 - t1, d2 = o2 - t2, d3 = o3 - t3;
        float s0 = fabsf(d0) < 1.f ? 0.5f * d0 * d0 : fabsf(d0) - 0.5f;
        float s1 = fabsf(d1) < 1.f ? 0.5f * d1 * d1 : fabsf(d1) - 0.5f;
        float s2 = fabsf(d2) < 1.f ? 0.5f * d2 * d2 : fabsf(d2) - 0.5f;
        float s3 = fabsf(d3) < 1.f ? 0.5f * d3 * d3 : fabsf(d3) - 0.5f;
        regv = s0 + s1 + s2 + s3;
    }

    float pcx = acx + o0 * aw, pcy = acy + o1 * ah;
    float pw = aw * expf(o2), ph = ah * expf(o3);
    float* pr = out + 1 + (size_t)gid * 4;
    pr[0] = (pcx - pw * 0.5f) * posf;
    pr[1] = (pcy - ph * 0.5f) * posf;
    pr[2] = (pcx + pw * 0.5f) * posf;
    pr[3] = (pcy + ph * 0.5f) * posf;
    out[1 + (size_t)BB * NN * 4 + gid] = posf;

    redc[tid] = clsv; redr[tid] = regv;
    __syncthreads();
    for (int s = 128; s > 0; s >>= 1) {
        if (tid < s) { redc[tid] += redc[tid + s]; redr[tid] += redr[tid + s]; }
        __syncthreads();
    }
    if (tid == 0) { g_clsp[blockIdx.x] = redc[0]; g_regp[blockIdx.x] = redr[0]; }
}

/* ============ kernel 5: finalize scalar loss ============================ */
__global__ void k_fin(float* __restrict__ out) {
    float c = 0.f, r = 0.f;
    for (int i = 0; i < 144; i++) { c += g_clsp[i]; r += g_regp[i]; }
    out[0] = (c + 5.f * r) * 0.25f;
}

/* ============ launch ==================================================== */
extern "C" void kernel_launch(void* const* d_in, const int* in_sizes, int n_in,
                              void* d_out, int out_size) {
    const float* fm  = (const float*)d_in[0];
    const float* gtb = (const float*)d_in[1];
    const float* w1  = (const float*)d_in[3];
    const float* b1  = (const float*)d_in[4];
    const float* cw  = (const float*)d_in[5];
    const float* cb  = (const float*)d_in[6];
    const float* rw  = (const float*)d_in[7];
    const float* rb  = (const float*)d_in[8];
    float* out = (float*)d_out;

    cudaFuncSetAttribute(k_convmma, cudaFuncAttributeMaxDynamicSharedMemorySize,
                         SMEM_BYTES);

    k_fmt<<<dim3(32, 64, 4), dim3(32, 8)>>>(fm);
    k_wpack<<<dim3(64, 16), 256>>>(w1);
    k_convmma<<<dim3(32, 4, KSPL), 256, SMEM_BYTES>>>();
    k_reduce<<<2048, 256>>>(b1);
    k_heads<<<512, 256>>>(cw, cb, rw, rb);
    k_maxpg<<<BB * GG, 256>>>(gtb);
    k_loss<<<144, 256>>>(gtb, out);
    k_fin<<<1, 1>>>(out);
}